// round 15
// baseline (speedup 1.0000x reference)
#include <cuda_runtime.h>
#include <cuda_fp16.h>
#include <cstdint>

#define NPTS 512
#define HDIM 128
#define TP 128
#define NPAIRS 130816
#define NTILES 1022
#define NBATCH 8
#define NB_BLK 4
#define GRIDY (NBATCH / NB_BLK)
#define THREADS 256
#define BSTRIDE 136       // fp16 per B row (272B, conflict-free ldsm)

struct Smem {
    __half bmat[HDIM * BSTRIDE];   // W2^T fp16  [d][k]
    float w1s[3 * HDIM];
    float b1s[HDIM];
    float b2s[HDIM];
    float w3s[HDIM];
    float red[NB_BLK][8];
};

__device__ __align__(16) __half g_bmat[HDIM * BSTRIDE];

// ---------------- f32x2 packed helpers ----------------
__device__ __forceinline__ uint64_t pk2(float a, float b) {
    uint64_t r; asm("mov.b64 %0, {%1,%2};" : "=l"(r) : "f"(a), "f"(b)); return r;
}
__device__ __forceinline__ void upk2(uint64_t v, float& a, float& b) {
    asm("mov.b64 {%0,%1}, %2;" : "=f"(a), "=f"(b) : "l"(v));
}
__device__ __forceinline__ uint64_t fma2(uint64_t a, uint64_t b, uint64_t c) {
    uint64_t d; asm("fma.rn.f32x2 %0, %1, %2, %3;" : "=l"(d) : "l"(a), "l"(b), "l"(c)); return d;
}
__device__ __forceinline__ uint64_t add2(uint64_t a, uint64_t b) {
    uint64_t d; asm("add.rn.f32x2 %0, %1, %2;" : "=l"(d) : "l"(a), "l"(b)); return d;
}

// pack (lo, hi) floats into f16x2
__device__ __forceinline__ uint32_t pack_f16(float lo, float hi) {
    uint32_t r;
    asm("cvt.rn.f16x2.f32 %0, %1, %2;" : "=r"(r) : "f"(hi), "f"(lo));
    return r;
}

// silu(z) = z * sigmoid(z) = 0.5z*tanh(z/2) + 0.5z ; 1 MUFU + 2 FMA per value
__device__ __forceinline__ uint32_t silu2_tanh_f16(uint64_t z2) {
    float z0, z1; upk2(z2, z0, z1);
    float h0 = 0.5f * z0, h1 = 0.5f * z1;
    float t0, t1;
    asm("tanh.approx.f32 %0, %1;" : "=f"(t0) : "f"(h0));
    asm("tanh.approx.f32 %0, %1;" : "=f"(t1) : "f"(h1));
    return pack_f16(fmaf(h0, t0, h0), fmaf(h1, t1, h1));
}

// epilogue silu (fp32 packed result), same tanh form
__device__ __forceinline__ uint64_t silu2_tanh(uint64_t z2) {
    float z0, z1; upk2(z2, z0, z1);
    float h0 = 0.5f * z0, h1 = 0.5f * z1;
    float t0, t1;
    asm("tanh.approx.f32 %0, %1;" : "=f"(t0) : "f"(h0));
    asm("tanh.approx.f32 %0, %1;" : "=f"(t1) : "f"(h1));
    return pk2(fmaf(h0, t0, h0), fmaf(h1, t1, h1));
}

__device__ __forceinline__ void ldsm_x4(uint32_t& r0, uint32_t& r1, uint32_t& r2, uint32_t& r3,
                                        uint32_t addr) {
    asm volatile("ldmatrix.sync.aligned.m8n8.x4.shared.b16 {%0,%1,%2,%3}, [%4];"
                 : "=r"(r0), "=r"(r1), "=r"(r2), "=r"(r3) : "r"(addr));
}
__device__ __forceinline__ void mma_f16(float* c, const uint32_t* a, uint32_t b0, uint32_t b1) {
    asm volatile(
        "mma.sync.aligned.m16n8k16.row.col.f32.f16.f16.f32 "
        "{%0,%1,%2,%3}, {%4,%5,%6,%7}, {%8,%9}, {%0,%1,%2,%3};"
        : "+f"(c[0]), "+f"(c[1]), "+f"(c[2]), "+f"(c[3])
        : "r"(a[0]), "r"(a[1]), "r"(a[2]), "r"(a[3]), "r"(b0), "r"(b1));
}
__device__ __forceinline__ uint32_t smem_u32(const void* p) {
    uint32_t a;
    asm("{ .reg .u64 t; cvta.to.shared.u64 t, %1; cvt.u32.u64 %0, t; }" : "=r"(a) : "l"(p));
    return a;
}

// ---------------- kernels ----------------
__global__ void init_out_kernel(float* out, const float* b3) {
    int b = threadIdx.x;
    if (b < NBATCH) out[b] = (float)NPAIRS * b3[0];
}

__global__ void prep_kernel(const float* __restrict__ W2) {
    int idx = blockIdx.x * blockDim.x + threadIdx.x;
    if (idx >= HDIM * HDIM) return;
    int d = idx & 127;
    int k = idx >> 7;
    g_bmat[d * BSTRIDE + k] = __float2half(W2[idx]);   // W2[k][d] -> B[d][k]
}

__global__ __launch_bounds__(THREADS, 2)
void discovery_hmma(const float* __restrict__ pos,
                    const float* __restrict__ W1,
                    const float* __restrict__ b1,
                    const float* __restrict__ b2,
                    const float* __restrict__ W3,
                    float* __restrict__ out) {
    extern __shared__ char smem_raw[];
    Smem* s = reinterpret_cast<Smem*>(smem_raw);

    const int t = threadIdx.x;
    const int w = t >> 5;
    const int lane = t & 31;
    const int tile = blockIdx.x;
    const int b0 = blockIdx.y * NB_BLK;

    // ---- stage weights ----
    {
        const uint4* src = (const uint4*)g_bmat;
        uint4* dst = (uint4*)s->bmat;
        for (int i = t; i < (HDIM * BSTRIDE) / 8; i += THREADS) dst[i] = src[i];
    }
    for (int i = t; i < 3 * HDIM; i += THREADS) s->w1s[i] = W1[i];
    if (t < HDIM) {
        s->b1s[t] = b1[t];
        s->b2s[t] = b2[t];
        s->w3s[t] = W3[t];
    }

    // ---- pair decode: 2 pairs per thread (rows r, r+8 of this warp's 16) ----
    int ip[2], jp[2];
    {
        const int mrow = w * 16 + (lane >> 2);
        #pragma unroll
        for (int q = 0; q < 2; ++q) {
            int p = tile * TP + mrow + q * 8;
            double tn = 2.0 * NPTS - 1.0;
            int i = (int)floor((tn - sqrt(tn * tn - 8.0 * (double)p)) * 0.5);
            if (i < 0) i = 0;
            while ((long)(i + 1) * (2 * NPTS - 1 - (i + 1)) / 2 <= p) i++;
            while ((long)i * (2 * NPTS - 1 - i) / 2 > p) i--;
            long s0 = (long)i * (2 * NPTS - 1 - i) / 2;
            ip[q] = i;
            jp[q] = i + 1 + (int)(p - s0);
        }
    }
    __syncthreads();

    const uint32_t b_base = smem_u32(s->bmat);
    const int rowoff = (lane & 7) + ((lane >> 4) << 3);
    const int kadd   = ((lane >> 3) & 1) << 3;
    const uint32_t laneB = (uint32_t)(rowoff * BSTRIDE + kadd) * 2u + b_base;
    const int kcol = (lane & 3) * 2;

    for (int bb = 0; bb < NB_BLK; ++bb) {
        const int b = b0 + bb;

        // ---- features ----
        uint64_t F0[2], F1[2], F2[2];
        {
            const float* pb = pos + (size_t)b * NPTS * 3;
            #pragma unroll
            for (int q = 0; q < 2; ++q) {
                int i = ip[q], j = jp[q];
                float dx = pb[i * 3 + 0] - pb[j * 3 + 0];
                float dy = pb[i * 3 + 1] - pb[j * 3 + 1];
                float dz = pb[i * 3 + 2] - pb[j * 3 + 2];
                float r = sqrtf(dx * dx + dy * dy + dz * dz);
                r = fmaxf(r, 0.05f);
                float ri = 1.0f / r;
                F0[q] = pk2(r, r);
                F1[q] = pk2(ri, ri);
                F2[q] = pk2(ri * ri, ri * ri);
            }
        }

        // ---- build ALL A fragments for this batch (8 k-steps x 4 regs) ----
        uint32_t afr[8][4];
        #pragma unroll
        for (int ks = 0; ks < 8; ++ks) {
            const int k0 = ks * 16 + kcol;
            float2 va0 = *(const float2*)&s->w1s[k0];
            float2 va8 = *(const float2*)&s->w1s[k0 + 8];
            float2 vb0 = *(const float2*)&s->w1s[128 + k0];
            float2 vb8 = *(const float2*)&s->w1s[128 + k0 + 8];
            float2 vc0 = *(const float2*)&s->w1s[256 + k0];
            float2 vc8 = *(const float2*)&s->w1s[256 + k0 + 8];
            float2 vd0 = *(const float2*)&s->b1s[k0];
            float2 vd8 = *(const float2*)&s->b1s[k0 + 8];
            uint64_t wa0 = pk2(va0.x, va0.y), wa8 = pk2(va8.x, va8.y);
            uint64_t wb0 = pk2(vb0.x, vb0.y), wb8 = pk2(vb8.x, vb8.y);
            uint64_t wc0 = pk2(vc0.x, vc0.y), wc8 = pk2(vc8.x, vc8.y);
            uint64_t bbv0 = pk2(vd0.x, vd0.y), bbv8 = pk2(vd8.x, vd8.y);

            uint64_t z00 = fma2(wc0, F2[0], fma2(wb0, F1[0], fma2(wa0, F0[0], bbv0)));
            uint64_t z10 = fma2(wc0, F2[1], fma2(wb0, F1[1], fma2(wa0, F0[1], bbv0)));
            uint64_t z08 = fma2(wc8, F2[0], fma2(wb8, F1[0], fma2(wa8, F0[0], bbv8)));
            uint64_t z18 = fma2(wc8, F2[1], fma2(wb8, F1[1], fma2(wa8, F0[1], bbv8)));
            afr[ks][0] = silu2_tanh_f16(z00);   // (q0; k0,k0+1)
            afr[ks][1] = silu2_tanh_f16(z10);   // (q1; k0,k0+1)
            afr[ks][2] = silu2_tanh_f16(z08);   // (q0; k0+8,k0+9)
            afr[ks][3] = silu2_tanh_f16(z18);   // (q1; k0+8,k0+9)
        }

        // ---- per column-pair: accumulate over k, then fused epilogue ----
        uint64_t sum2 = 0;
        #pragma unroll
        for (int pr = 0; pr < 8; ++pr) {
            float acc0[4] = {0.f, 0.f, 0.f, 0.f};
            float acc1[4] = {0.f, 0.f, 0.f, 0.f};
            const uint32_t prbase = laneB + (uint32_t)((pr * 16) * BSTRIDE) * 2u;
            #pragma unroll
            for (int ks = 0; ks < 8; ++ks) {
                uint32_t h0, h1v, h2v, h3v;
                ldsm_x4(h0, h1v, h2v, h3v, prbase + (uint32_t)(ks * 16) * 2u);
                mma_f16(acc0, afr[ks], h0,  h1v);
                mma_f16(acc1, afr[ks], h2v, h3v);
            }
            // epilogue for cols pr*16 + kcol (+0/+8)
            {
                int col = pr * 16 + kcol;
                float2 b2a = *(const float2*)&s->b2s[col];
                float2 w3a = *(const float2*)&s->w3s[col];
                float2 b2b = *(const float2*)&s->b2s[col + 8];
                float2 w3b = *(const float2*)&s->w3s[col + 8];
                uint64_t b2va = pk2(b2a.x, b2a.y), w3va = pk2(w3a.x, w3a.y);
                uint64_t b2vb = pk2(b2b.x, b2b.y), w3vb = pk2(w3b.x, w3b.y);
                uint64_t za0 = add2(pk2(acc0[0], acc0[1]), b2va);
                uint64_t za1 = add2(pk2(acc0[2], acc0[3]), b2va);
                uint64_t zb0 = add2(pk2(acc1[0], acc1[1]), b2vb);
                uint64_t zb1 = add2(pk2(acc1[2], acc1[3]), b2vb);
                sum2 = fma2(silu2_tanh(za0), w3va, sum2);
                sum2 = fma2(silu2_tanh(za1), w3va, sum2);
                sum2 = fma2(silu2_tanh(zb0), w3vb, sum2);
                sum2 = fma2(silu2_tanh(zb1), w3vb, sum2);
            }
        }
        float sa, sb;
        upk2(sum2, sa, sb);
        float sum = sa + sb;

        #pragma unroll
        for (int off = 16; off > 0; off >>= 1)
            sum += __shfl_xor_sync(0xFFFFFFFFu, sum, off);
        if (lane == 0) s->red[bb][w] = sum;
    }

    __syncthreads();
    if (w == 0 && lane < NB_BLK) {
        float tot = 0.0f;
        #pragma unroll
        for (int wi = 0; wi < 8; ++wi) tot += s->red[lane][wi];
        atomicAdd(&out[b0 + lane], tot);
    }
}

extern "C" void kernel_launch(void* const* d_in, const int* in_sizes, int n_in,
                              void* d_out, int out_size) {
    const float* pos = (const float*)d_in[0];
    const float* W1  = (const float*)d_in[1];
    const float* b1  = (const float*)d_in[2];
    const float* W2  = (const float*)d_in[3];
    const float* b2  = (const float*)d_in[4];
    const float* W3  = (const float*)d_in[5];
    const float* b3  = (const float*)d_in[6];
    float* out = (float*)d_out;

    cudaFuncSetAttribute(discovery_hmma,
                         cudaFuncAttributeMaxDynamicSharedMemorySize, (int)sizeof(Smem));

    init_out_kernel<<<1, NBATCH>>>(out, b3);
    prep_kernel<<<64, 256>>>(W2);
    dim3 grid(NTILES, GRIDY);
    discovery_hmma<<<grid, THREADS, sizeof(Smem)>>>(pos, W1, b1, b2, W3, out);
}

// round 17
// speedup vs baseline: 1.0098x; 1.0098x over previous
#include <cuda_runtime.h>
#include <cuda_fp16.h>
#include <cstdint>

#define NPTS 512
#define HDIM 128
#define TP 128
#define NPAIRS 130816
#define NTILES 1022
#define NBATCH 8
#define NB_BLK 4
#define GRIDY (NBATCH / NB_BLK)
#define THREADS 256
#define BSTRIDE 136       // fp16 per B row (272B, conflict-free ldsm)

struct Smem {
    __half bmat[HDIM * BSTRIDE];   // W2^T fp16  [d][k]
    float w1s[3 * HDIM];
    float b1s[HDIM];
    float b2s[HDIM];
    float w3s[HDIM];
    float red[NB_BLK][8];
};

__device__ __align__(16) __half g_bmat[HDIM * BSTRIDE];

// ---------------- f32x2 packed helpers ----------------
__device__ __forceinline__ uint64_t pk2(float a, float b) {
    uint64_t r; asm("mov.b64 %0, {%1,%2};" : "=l"(r) : "f"(a), "f"(b)); return r;
}
__device__ __forceinline__ void upk2(uint64_t v, float& a, float& b) {
    asm("mov.b64 {%0,%1}, %2;" : "=f"(a), "=f"(b) : "l"(v));
}
__device__ __forceinline__ uint64_t fma2(uint64_t a, uint64_t b, uint64_t c) {
    uint64_t d; asm("fma.rn.f32x2 %0, %1, %2, %3;" : "=l"(d) : "l"(a), "l"(b), "l"(c)); return d;
}
__device__ __forceinline__ uint64_t add2(uint64_t a, uint64_t b) {
    uint64_t d; asm("add.rn.f32x2 %0, %1, %2;" : "=l"(d) : "l"(a), "l"(b)); return d;
}

// pack (lo, hi) floats into f16x2
__device__ __forceinline__ uint32_t pack_f16(float lo, float hi) {
    uint32_t r;
    asm("cvt.rn.f16x2.f32 %0, %1, %2;" : "=r"(r) : "f"(hi), "f"(lo));
    return r;
}

// silu(z) = z * sigmoid(z) = 0.5z*tanh(z/2) + 0.5z ; 1 MUFU + 2 FMA per value
__device__ __forceinline__ uint32_t silu2_tanh_f16(uint64_t z2) {
    float z0, z1; upk2(z2, z0, z1);
    float h0 = 0.5f * z0, h1 = 0.5f * z1;
    float t0, t1;
    asm("tanh.approx.f32 %0, %1;" : "=f"(t0) : "f"(h0));
    asm("tanh.approx.f32 %0, %1;" : "=f"(t1) : "f"(h1));
    return pack_f16(fmaf(h0, t0, h0), fmaf(h1, t1, h1));
}

// epilogue silu (fp32 packed result), same tanh form
__device__ __forceinline__ uint64_t silu2_tanh(uint64_t z2) {
    float z0, z1; upk2(z2, z0, z1);
    float h0 = 0.5f * z0, h1 = 0.5f * z1;
    float t0, t1;
    asm("tanh.approx.f32 %0, %1;" : "=f"(t0) : "f"(h0));
    asm("tanh.approx.f32 %0, %1;" : "=f"(t1) : "f"(h1));
    return pk2(fmaf(h0, t0, h0), fmaf(h1, t1, h1));
}

__device__ __forceinline__ void ldsm_x4(uint32_t& r0, uint32_t& r1, uint32_t& r2, uint32_t& r3,
                                        uint32_t addr) {
    asm volatile("ldmatrix.sync.aligned.m8n8.x4.shared.b16 {%0,%1,%2,%3}, [%4];"
                 : "=r"(r0), "=r"(r1), "=r"(r2), "=r"(r3) : "r"(addr));
}
__device__ __forceinline__ void mma_f16(float* c, const uint32_t* a, uint32_t b0, uint32_t b1) {
    asm volatile(
        "mma.sync.aligned.m16n8k16.row.col.f32.f16.f16.f32 "
        "{%0,%1,%2,%3}, {%4,%5,%6,%7}, {%8,%9}, {%0,%1,%2,%3};"
        : "+f"(c[0]), "+f"(c[1]), "+f"(c[2]), "+f"(c[3])
        : "r"(a[0]), "r"(a[1]), "r"(a[2]), "r"(a[3]), "r"(b0), "r"(b1));
}
__device__ __forceinline__ uint32_t smem_u32(const void* p) {
    uint32_t a;
    asm("{ .reg .u64 t; cvta.to.shared.u64 t, %1; cvt.u32.u64 %0, t; }" : "=r"(a) : "l"(p));
    return a;
}

// ---------------- kernels ----------------
__global__ void init_out_kernel(float* out, const float* b3) {
    int b = threadIdx.x;
    if (b < NBATCH) out[b] = (float)NPAIRS * b3[0];
}

__global__ void prep_kernel(const float* __restrict__ W2) {
    int idx = blockIdx.x * blockDim.x + threadIdx.x;
    if (idx >= HDIM * HDIM) return;
    int d = idx & 127;
    int k = idx >> 7;
    g_bmat[d * BSTRIDE + k] = __float2half(W2[idx]);   // W2[k][d] -> B[d][k]
}

__global__ __launch_bounds__(THREADS, 2)
void discovery_hmma(const float* __restrict__ pos,
                    const float* __restrict__ W1,
                    const float* __restrict__ b1,
                    const float* __restrict__ b2,
                    const float* __restrict__ W3,
                    float* __restrict__ out) {
    extern __shared__ char smem_raw[];
    Smem* s = reinterpret_cast<Smem*>(smem_raw);

    const int t = threadIdx.x;
    const int w = t >> 5;
    const int lane = t & 31;
    const int tile = blockIdx.x;
    const int b0 = blockIdx.y * NB_BLK;

    // ---- stage weights ----
    {
        const uint4* src = (const uint4*)g_bmat;
        uint4* dst = (uint4*)s->bmat;
        for (int i = t; i < (HDIM * BSTRIDE) / 8; i += THREADS) dst[i] = src[i];
    }
    for (int i = t; i < 3 * HDIM; i += THREADS) s->w1s[i] = W1[i];
    if (t < HDIM) {
        s->b1s[t] = b1[t];
        s->b2s[t] = b2[t];
        s->w3s[t] = W3[t];
    }

    // ---- pair decode: 2 pairs per thread (rows r, r+8 of this warp's 16) ----
    int ip[2], jp[2];
    {
        const int mrow = w * 16 + (lane >> 2);
        #pragma unroll
        for (int q = 0; q < 2; ++q) {
            int p = tile * TP + mrow + q * 8;
            double tn = 2.0 * NPTS - 1.0;
            int i = (int)floor((tn - sqrt(tn * tn - 8.0 * (double)p)) * 0.5);
            if (i < 0) i = 0;
            while ((long)(i + 1) * (2 * NPTS - 1 - (i + 1)) / 2 <= p) i++;
            while ((long)i * (2 * NPTS - 1 - i) / 2 > p) i--;
            long s0 = (long)i * (2 * NPTS - 1 - i) / 2;
            ip[q] = i;
            jp[q] = i + 1 + (int)(p - s0);
        }
    }
    __syncthreads();

    const uint32_t b_base = smem_u32(s->bmat);
    const int rowoff = (lane & 7) + ((lane >> 4) << 3);
    const int kadd   = ((lane >> 3) & 1) << 3;
    const uint32_t laneB = (uint32_t)(rowoff * BSTRIDE + kadd) * 2u + b_base;
    const int kcol = (lane & 3) * 2;

    for (int bb = 0; bb < NB_BLK; ++bb) {
        const int b = b0 + bb;

        // ---- features ----
        uint64_t F0[2], F1[2], F2[2];
        {
            const float* pb = pos + (size_t)b * NPTS * 3;
            #pragma unroll
            for (int q = 0; q < 2; ++q) {
                int i = ip[q], j = jp[q];
                float dx = pb[i * 3 + 0] - pb[j * 3 + 0];
                float dy = pb[i * 3 + 1] - pb[j * 3 + 1];
                float dz = pb[i * 3 + 2] - pb[j * 3 + 2];
                float r = sqrtf(dx * dx + dy * dy + dz * dz);
                r = fmaxf(r, 0.05f);
                float ri = 1.0f / r;
                F0[q] = pk2(r, r);
                F1[q] = pk2(ri, ri);
                F2[q] = pk2(ri * ri, ri * ri);
            }
        }

        // ---- build ALL A fragments for this batch (8 k-steps x 4 regs) ----
        uint32_t afr[8][4];
        #pragma unroll
        for (int ks = 0; ks < 8; ++ks) {
            const int k0 = ks * 16 + kcol;
            float2 va0 = *(const float2*)&s->w1s[k0];
            float2 va8 = *(const float2*)&s->w1s[k0 + 8];
            float2 vb0 = *(const float2*)&s->w1s[128 + k0];
            float2 vb8 = *(const float2*)&s->w1s[128 + k0 + 8];
            float2 vc0 = *(const float2*)&s->w1s[256 + k0];
            float2 vc8 = *(const float2*)&s->w1s[256 + k0 + 8];
            float2 vd0 = *(const float2*)&s->b1s[k0];
            float2 vd8 = *(const float2*)&s->b1s[k0 + 8];
            uint64_t wa0 = pk2(va0.x, va0.y), wa8 = pk2(va8.x, va8.y);
            uint64_t wb0 = pk2(vb0.x, vb0.y), wb8 = pk2(vb8.x, vb8.y);
            uint64_t wc0 = pk2(vc0.x, vc0.y), wc8 = pk2(vc8.x, vc8.y);
            uint64_t bbv0 = pk2(vd0.x, vd0.y), bbv8 = pk2(vd8.x, vd8.y);

            uint64_t z00 = fma2(wc0, F2[0], fma2(wb0, F1[0], fma2(wa0, F0[0], bbv0)));
            uint64_t z10 = fma2(wc0, F2[1], fma2(wb0, F1[1], fma2(wa0, F0[1], bbv0)));
            uint64_t z08 = fma2(wc8, F2[0], fma2(wb8, F1[0], fma2(wa8, F0[0], bbv8)));
            uint64_t z18 = fma2(wc8, F2[1], fma2(wb8, F1[1], fma2(wa8, F0[1], bbv8)));
            afr[ks][0] = silu2_tanh_f16(z00);   // (q0; k0,k0+1)
            afr[ks][1] = silu2_tanh_f16(z10);   // (q1; k0,k0+1)
            afr[ks][2] = silu2_tanh_f16(z08);   // (q0; k0+8,k0+9)
            afr[ks][3] = silu2_tanh_f16(z18);   // (q1; k0+8,k0+9)
        }

        // ---- per column-pair: accumulate over k, then fused epilogue ----
        uint64_t sum2 = 0;
        #pragma unroll
        for (int pr = 0; pr < 8; ++pr) {
            float acc0[4] = {0.f, 0.f, 0.f, 0.f};
            float acc1[4] = {0.f, 0.f, 0.f, 0.f};
            const uint32_t prbase = laneB + (uint32_t)((pr * 16) * BSTRIDE) * 2u;
            #pragma unroll
            for (int ks = 0; ks < 8; ++ks) {
                uint32_t h0, h1v, h2v, h3v;
                ldsm_x4(h0, h1v, h2v, h3v, prbase + (uint32_t)(ks * 16) * 2u);
                mma_f16(acc0, afr[ks], h0,  h1v);
                mma_f16(acc1, afr[ks], h2v, h3v);
            }
            // epilogue for cols pr*16 + kcol (+0/+8)
            {
                int col = pr * 16 + kcol;
                float2 b2a = *(const float2*)&s->b2s[col];
                float2 w3a = *(const float2*)&s->w3s[col];
                float2 b2b = *(const float2*)&s->b2s[col + 8];
                float2 w3b = *(const float2*)&s->w3s[col + 8];
                uint64_t b2va = pk2(b2a.x, b2a.y), w3va = pk2(w3a.x, w3a.y);
                uint64_t b2vb = pk2(b2b.x, b2b.y), w3vb = pk2(w3b.x, w3b.y);
                uint64_t za0 = add2(pk2(acc0[0], acc0[1]), b2va);
                uint64_t za1 = add2(pk2(acc0[2], acc0[3]), b2va);
                uint64_t zb0 = add2(pk2(acc1[0], acc1[1]), b2vb);
                uint64_t zb1 = add2(pk2(acc1[2], acc1[3]), b2vb);
                sum2 = fma2(silu2_tanh(za0), w3va, sum2);
                sum2 = fma2(silu2_tanh(za1), w3va, sum2);
                sum2 = fma2(silu2_tanh(zb0), w3vb, sum2);
                sum2 = fma2(silu2_tanh(zb1), w3vb, sum2);
            }
        }
        float sa, sb;
        upk2(sum2, sa, sb);
        float sum = sa + sb;

        #pragma unroll
        for (int off = 16; off > 0; off >>= 1)
            sum += __shfl_xor_sync(0xFFFFFFFFu, sum, off);
        if (lane == 0) s->red[bb][w] = sum;
    }

    __syncthreads();
    if (w == 0 && lane < NB_BLK) {
        float tot = 0.0f;
        #pragma unroll
        for (int wi = 0; wi < 8; ++wi) tot += s->red[lane][wi];
        atomicAdd(&out[b0 + lane], tot);
    }
}

extern "C" void kernel_launch(void* const* d_in, const int* in_sizes, int n_in,
                              void* d_out, int out_size) {
    const float* pos = (const float*)d_in[0];
    const float* W1  = (const float*)d_in[1];
    const float* b1  = (const float*)d_in[2];
    const float* W2  = (const float*)d_in[3];
    const float* b2  = (const float*)d_in[4];
    const float* W3  = (const float*)d_in[5];
    const float* b3  = (const float*)d_in[6];
    float* out = (float*)d_out;

    cudaFuncSetAttribute(discovery_hmma,
                         cudaFuncAttributeMaxDynamicSharedMemorySize, (int)sizeof(Smem));

    init_out_kernel<<<1, NBATCH>>>(out, b3);
    prep_kernel<<<64, 256>>>(W2);
    dim3 grid(NTILES, GRIDY);
    discovery_hmma<<<grid, THREADS, sizeof(Smem)>>>(pos, W1, b1, b2, W3, out);
}